// round 1
// baseline (speedup 1.0000x reference)
#include <cuda_runtime.h>
#include <math.h>

#define NE 8
#define HID 2048
#define INTER 1408
#define TOT 8192
#define MAXTILES 96
#define MAXGRIDY 72   // sum_e ceil(n_e/128) <= TOT/128 + NE = 72

// ---- tile table (written by setup kernel, read by GEMM kernels) ----
__device__ int g_tile_expert[MAXTILES];
__device__ int g_tile_row0[MAXTILES];
__device__ int g_tile_nrows[MAXTILES];
__device__ int g_ntiles;

// ---- scratch for h = silu(gate)*up : [TOT, INTER] fp32 (46 MB) ----
__device__ float g_h[(size_t)TOT * INTER];

// ============================================================================
// Setup: prefix-sum the ragged sizes into a flat list of 128-row tiles,
// each fully inside one expert segment.
// ============================================================================
__global__ void setup_tiles(const int* __restrict__ tpe) {
    int off = 0, nt = 0;
    for (int e = 0; e < NE; e++) {
        int n = tpe[e];
        for (int r = 0; r < n; r += 128) {
            g_tile_expert[nt] = e;
            g_tile_row0[nt]   = off + r;
            g_tile_nrows[nt]  = (n - r < 128) ? (n - r) : 128;
            nt++;
        }
        off += n;
    }
    g_ntiles = nt;
}

// ============================================================================
// Kernel 1: h = silu(x @ Wg[e]) * (x @ Wu[e])   (fused: one A tile, two B tiles)
// Tile: BM=128, BN=64, BK=8. 256 threads; per-thread 8x4 accum for EACH matrix.
// ============================================================================
__global__ void __launch_bounds__(256) k_gateup(
    const float* __restrict__ x,
    const float* __restrict__ wg,
    const float* __restrict__ wu)
{
    const int t = blockIdx.y;
    if (t >= g_ntiles) return;
    const int e     = g_tile_expert[t];
    const int row0  = g_tile_row0[t];
    const int nrows = g_tile_nrows[t];
    const int n0    = blockIdx.x * 64;

    const float* __restrict__ wge = wg + (size_t)e * HID * INTER;
    const float* __restrict__ wue = wu + (size_t)e * HID * INTER;

    __shared__ float As[2][8][128];
    __shared__ float Bg[2][8][64];
    __shared__ float Bu[2][8][64];

    const int tid  = threadIdx.x;
    // A-load mapping: 128 rows x 2 float4 per row = 256 float4
    const int ar   = tid >> 1;          // 0..127 (row in tile)
    const int ak   = (tid & 1) * 4;     // 0 or 4 (k offset)
    // B-load mapping: threads 0..127 -> gate tile, 128..255 -> up tile
    const int bsel = tid >> 7;
    const int btid = tid & 127;
    const int bk   = btid >> 4;         // 0..7
    const int bn   = (btid & 15) * 4;   // 0..60
    // compute mapping
    const int ty   = tid >> 4;          // 0..15 -> 8 rows
    const int tx   = tid & 15;          // 0..15 -> 4 cols

    const float* __restrict__ bptr = bsel ? wue : wge;

    float accg[8][4], accu[8][4];
    #pragma unroll
    for (int i = 0; i < 8; i++)
        #pragma unroll
        for (int j = 0; j < 4; j++) { accg[i][j] = 0.f; accu[i][j] = 0.f; }

    float4 areg, breg;
    if (ar < nrows) areg = *(const float4*)(x + (size_t)(row0 + ar) * HID + ak);
    else            areg = make_float4(0.f, 0.f, 0.f, 0.f);
    breg = *(const float4*)(bptr + (size_t)bk * INTER + n0 + bn);

    As[0][ak+0][ar] = areg.x; As[0][ak+1][ar] = areg.y;
    As[0][ak+2][ar] = areg.z; As[0][ak+3][ar] = areg.w;
    if (bsel) *(float4*)&Bu[0][bk][bn] = breg;
    else      *(float4*)&Bg[0][bk][bn] = breg;
    __syncthreads();

    const int KT = HID / 8;
    for (int kt = 0; kt < KT; kt++) {
        const int  cur      = kt & 1;
        const bool has_next = (kt + 1 < KT);
        if (has_next) {
            const int k0 = (kt + 1) * 8;
            if (ar < nrows) areg = *(const float4*)(x + (size_t)(row0 + ar) * HID + k0 + ak);
            else            areg = make_float4(0.f, 0.f, 0.f, 0.f);
            breg = *(const float4*)(bptr + (size_t)(k0 + bk) * INTER + n0 + bn);
        }
        #pragma unroll
        for (int k = 0; k < 8; k++) {
            float4 a0  = *(const float4*)&As[cur][k][ty * 8];
            float4 a1  = *(const float4*)&As[cur][k][ty * 8 + 4];
            float4 bg4 = *(const float4*)&Bg[cur][k][tx * 4];
            float4 bu4 = *(const float4*)&Bu[cur][k][tx * 4];
            float a[8]  = {a0.x, a0.y, a0.z, a0.w, a1.x, a1.y, a1.z, a1.w};
            float gg[4] = {bg4.x, bg4.y, bg4.z, bg4.w};
            float uu[4] = {bu4.x, bu4.y, bu4.z, bu4.w};
            #pragma unroll
            for (int i = 0; i < 8; i++)
                #pragma unroll
                for (int j = 0; j < 4; j++) {
                    accg[i][j] += a[i] * gg[j];
                    accu[i][j] += a[i] * uu[j];
                }
        }
        if (has_next) {
            const int nxt = cur ^ 1;
            As[nxt][ak+0][ar] = areg.x; As[nxt][ak+1][ar] = areg.y;
            As[nxt][ak+2][ar] = areg.z; As[nxt][ak+3][ar] = areg.w;
            if (bsel) *(float4*)&Bu[nxt][bk][bn] = breg;
            else      *(float4*)&Bg[nxt][bk][bn] = breg;
            __syncthreads();
        }
    }

    // epilogue: SiLU(gate) * up -> g_h
    #pragma unroll
    for (int i = 0; i < 8; i++) {
        const int r = ty * 8 + i;
        if (r < nrows) {
            float g0 = accg[i][0], g1 = accg[i][1], g2 = accg[i][2], g3 = accg[i][3];
            float4 o;
            o.x = accu[i][0] * (g0 / (1.f + __expf(-g0)));
            o.y = accu[i][1] * (g1 / (1.f + __expf(-g1)));
            o.z = accu[i][2] * (g2 / (1.f + __expf(-g2)));
            o.w = accu[i][3] * (g3 / (1.f + __expf(-g3)));
            *(float4*)(&g_h[(size_t)(row0 + r) * INTER + n0 + tx * 4]) = o;
        }
    }
}

// ============================================================================
// Kernel 2: out = probs[:,None] * (h @ Wd[e])
// Tile: BM=128, BN=128, BK=8. 256 threads; per-thread 8x8.
// ============================================================================
__global__ void __launch_bounds__(256) k_down(
    const float* __restrict__ probs,
    const float* __restrict__ wd,
    float* __restrict__ out)
{
    const int t = blockIdx.y;
    if (t >= g_ntiles) return;
    const int e     = g_tile_expert[t];
    const int row0  = g_tile_row0[t];
    const int nrows = g_tile_nrows[t];
    const int n0    = blockIdx.x * 128;

    const float* __restrict__ wde = wd + (size_t)e * INTER * HID;

    __shared__ float As[2][8][128];
    __shared__ float Bs[2][8][128];

    const int tid = threadIdx.x;
    const int ar  = tid >> 1;           // 0..127
    const int ak  = (tid & 1) * 4;      // 0 or 4
    const int bk  = tid >> 5;           // 0..7
    const int bn  = (tid & 31) * 4;     // 0..124
    const int ty  = tid >> 4;           // 0..15
    const int tx  = tid & 15;           // 0..15

    float acc[8][8];
    #pragma unroll
    for (int i = 0; i < 8; i++)
        #pragma unroll
        for (int j = 0; j < 8; j++) acc[i][j] = 0.f;

    float4 areg, breg;
    if (ar < nrows) areg = *(const float4*)(g_h + (size_t)(row0 + ar) * INTER + ak);
    else            areg = make_float4(0.f, 0.f, 0.f, 0.f);
    breg = *(const float4*)(wde + (size_t)bk * HID + n0 + bn);

    As[0][ak+0][ar] = areg.x; As[0][ak+1][ar] = areg.y;
    As[0][ak+2][ar] = areg.z; As[0][ak+3][ar] = areg.w;
    *(float4*)&Bs[0][bk][bn] = breg;
    __syncthreads();

    const int KT = INTER / 8;
    for (int kt = 0; kt < KT; kt++) {
        const int  cur      = kt & 1;
        const bool has_next = (kt + 1 < KT);
        if (has_next) {
            const int k0 = (kt + 1) * 8;
            if (ar < nrows) areg = *(const float4*)(g_h + (size_t)(row0 + ar) * INTER + k0 + ak);
            else            areg = make_float4(0.f, 0.f, 0.f, 0.f);
            breg = *(const float4*)(wde + (size_t)(k0 + bk) * HID + n0 + bn);
        }
        #pragma unroll
        for (int k = 0; k < 8; k++) {
            float4 a0 = *(const float4*)&As[cur][k][ty * 8];
            float4 a1 = *(const float4*)&As[cur][k][ty * 8 + 4];
            float4 b0 = *(const float4*)&Bs[cur][k][tx * 8];
            float4 b1 = *(const float4*)&Bs[cur][k][tx * 8 + 4];
            float a[8] = {a0.x, a0.y, a0.z, a0.w, a1.x, a1.y, a1.z, a1.w};
            float b[8] = {b0.x, b0.y, b0.z, b0.w, b1.x, b1.y, b1.z, b1.w};
            #pragma unroll
            for (int i = 0; i < 8; i++)
                #pragma unroll
                for (int j = 0; j < 8; j++)
                    acc[i][j] += a[i] * b[j];
        }
        if (has_next) {
            const int nxt = cur ^ 1;
            As[nxt][ak+0][ar] = areg.x; As[nxt][ak+1][ar] = areg.y;
            As[nxt][ak+2][ar] = areg.z; As[nxt][ak+3][ar] = areg.w;
            *(float4*)&Bs[nxt][bk][bn] = breg;
            __syncthreads();
        }
    }

    // epilogue: scale by probs, write out
    #pragma unroll
    for (int i = 0; i < 8; i++) {
        const int r = ty * 8 + i;
        if (r < nrows) {
            const float p = probs[row0 + r];
            float* op = out + (size_t)(row0 + r) * HID + n0 + tx * 8;
            float4 o0, o1;
            o0.x = p * acc[i][0]; o0.y = p * acc[i][1];
            o0.z = p * acc[i][2]; o0.w = p * acc[i][3];
            o1.x = p * acc[i][4]; o1.y = p * acc[i][5];
            o1.z = p * acc[i][6]; o1.w = p * acc[i][7];
            *(float4*)(op)     = o0;
            *(float4*)(op + 4) = o1;
        }
    }
}

// ============================================================================
// Launch
// ============================================================================
extern "C" void kernel_launch(void* const* d_in, const int* in_sizes, int n_in,
                              void* d_out, int out_size) {
    const float* x     = (const float*)d_in[0];
    const float* probs = (const float*)d_in[1];
    const float* wg    = (const float*)d_in[2];
    const float* wu    = (const float*)d_in[3];
    const float* wd    = (const float*)d_in[4];
    const int*   tpe   = (const int*)d_in[5];
    float*       out   = (float*)d_out;

    setup_tiles<<<1, 1>>>(tpe);

    dim3 g1(INTER / 64, MAXGRIDY);   // 22 x 72
    k_gateup<<<g1, 256>>>(x, wg, wu);

    dim3 g2(HID / 128, MAXGRIDY);    // 16 x 72
    k_down<<<g2, 256>>>(probs, wd, out);
}

// round 3
// speedup vs baseline: 2.1331x; 2.1331x over previous
#include <cuda_runtime.h>
#include <cuda_bf16.h>
#include <stdint.h>
#include <math.h>

#define NE 8
#define HID 2048
#define INTER 1408
#define TOT 8192
#define MAXTILES 96
#define MAXGRIDY 72

// ---------------------------------------------------------------------------
// Device globals (scratch; allocation-free rule)
// ---------------------------------------------------------------------------
__device__ int g_tile_expert[MAXTILES];
__device__ int g_tile_row0[MAXTILES];
__device__ int g_tile_nrows[MAXTILES];
__device__ int g_ntiles;

__device__ __nv_bfloat16 g_xh[(size_t)TOT * HID];
__device__ __nv_bfloat16 g_xl[(size_t)TOT * HID];
// transposed weights: [E][N][K], K contiguous
__device__ __nv_bfloat16 g_wgh[(size_t)NE * INTER * HID];
__device__ __nv_bfloat16 g_wgl[(size_t)NE * INTER * HID];
__device__ __nv_bfloat16 g_wuh[(size_t)NE * INTER * HID];
__device__ __nv_bfloat16 g_wul[(size_t)NE * INTER * HID];
__device__ __nv_bfloat16 g_wdh[(size_t)NE * HID * INTER];
__device__ __nv_bfloat16 g_wdl[(size_t)NE * HID * INTER];
__device__ __nv_bfloat16 g_hh[(size_t)TOT * INTER];
__device__ __nv_bfloat16 g_hl[(size_t)TOT * INTER];

// ---------------------------------------------------------------------------
// Helpers (base-target PTX only: sm_80-era mma.sync + cp.async)
// ---------------------------------------------------------------------------
__device__ __forceinline__ uint32_t smem_u32(const void* p) {
    uint32_t a;
    asm("{ .reg .u64 t; cvta.to.shared.u64 t, %1; cvt.u32.u64 %0, t; }"
        : "=r"(a) : "l"(p));
    return a;
}

__device__ __forceinline__ void cp16(uint32_t dst, const void* src, int srcsize) {
    asm volatile("cp.async.cg.shared.global [%0], [%1], 16, %2;"
                 :: "r"(dst), "l"(src), "r"(srcsize));
}
#define CP_COMMIT() asm volatile("cp.async.commit_group;")
#define CP_WAIT1()  asm volatile("cp.async.wait_group 1;")
#define CP_WAIT0()  asm volatile("cp.async.wait_group 0;")

__device__ __forceinline__ void mma16816(float& c0, float& c1, float& c2, float& c3,
                                         const uint32_t a[4], const uint32_t b[2]) {
    asm volatile(
        "mma.sync.aligned.m16n8k16.row.col.f32.bf16.bf16.f32 "
        "{%0,%1,%2,%3},{%4,%5,%6,%7},{%8,%9},{%0,%1,%2,%3};"
        : "+f"(c0), "+f"(c1), "+f"(c2), "+f"(c3)
        : "r"(a[0]), "r"(a[1]), "r"(a[2]), "r"(a[3]), "r"(b[0]), "r"(b[1]));
}
#define MMA(C, A, B) mma16816((C)[0], (C)[1], (C)[2], (C)[3], A, B)

// Tile in smem: rows x 32 bf16, row stride 80 bytes (20 banks -> conflict-free)
#define RSTR 80

// A fragment (16x16): a0=(r,k) a1=(r+8,k) a2=(r,k+8) a3=(r+8,k+8)
__device__ __forceinline__ void ldfragA(uint32_t a[4], const char* t, int rb, int k0, int lane) {
    const char* p = t + (rb + (lane >> 2)) * RSTR + (k0 + (lane & 3) * 2) * 2;
    a[0] = *(const uint32_t*)(p);
    a[1] = *(const uint32_t*)(p + 8 * RSTR);
    a[2] = *(const uint32_t*)(p + 16);
    a[3] = *(const uint32_t*)(p + 8 * RSTR + 16);
}
// B fragment (16x8, B stored [n][k] k-contiguous): b0=(k,n) b1=(k+8,n)
__device__ __forceinline__ void ldfragB(uint32_t b[2], const char* t, int nb, int k0, int lane) {
    const char* p = t + (nb + (lane >> 2)) * RSTR + (k0 + (lane & 3) * 2) * 2;
    b[0] = *(const uint32_t*)(p);
    b[1] = *(const uint32_t*)(p + 16);
}

// load 128-row x 32-col bf16 tile via cp.async (zero-fill invalid rows)
__device__ __forceinline__ void load_tile128(uint32_t sdst, const __nv_bfloat16* src,
                                             int ldk, int k0, int nvalid, int tid) {
#pragma unroll
    for (int i = 0; i < 2; i++) {
        int id = tid + i * 256;
        int r = id >> 2, c = id & 3;
        cp16(sdst + r * RSTR + c * 16, src + (size_t)r * ldk + k0 + c * 8,
             r < nvalid ? 16 : 0);
    }
}
// load 64-row x 32-col tile (always full)
__device__ __forceinline__ void load_tile64(uint32_t sdst, const __nv_bfloat16* src,
                                            int ldk, int k0, int tid) {
    int r = tid >> 2, c = tid & 3;
    cp16(sdst + r * RSTR + c * 16, src + (size_t)r * ldk + k0 + c * 8, 16);
}

// ---------------------------------------------------------------------------
// Setup + conversion kernels
// ---------------------------------------------------------------------------
__global__ void setup_tiles(const int* __restrict__ tpe) {
    int off = 0, nt = 0;
    for (int e = 0; e < NE; e++) {
        int n = tpe[e];
        for (int r = 0; r < n; r += 128) {
            g_tile_expert[nt] = e;
            g_tile_row0[nt]   = off + r;
            g_tile_nrows[nt]  = (n - r < 128) ? (n - r) : 128;
            nt++;
        }
        off += n;
    }
    g_ntiles = nt;
}

__global__ void convert_x(const float* __restrict__ x) {
    const size_t n4 = (size_t)TOT * HID / 4;
    for (size_t i = blockIdx.x * blockDim.x + threadIdx.x; i < n4;
         i += (size_t)gridDim.x * blockDim.x) {
        float4 v = ((const float4*)x)[i];
        __nv_bfloat16 h0 = __float2bfloat16(v.x), h1 = __float2bfloat16(v.y);
        __nv_bfloat16 h2 = __float2bfloat16(v.z), h3 = __float2bfloat16(v.w);
        __nv_bfloat16 l0 = __float2bfloat16(v.x - __bfloat162float(h0));
        __nv_bfloat16 l1 = __float2bfloat16(v.y - __bfloat162float(h1));
        __nv_bfloat16 l2 = __float2bfloat16(v.z - __bfloat162float(h2));
        __nv_bfloat16 l3 = __float2bfloat16(v.w - __bfloat162float(h3));
        uint32_t ph0 = (uint32_t)__bfloat16_as_ushort(h0) | ((uint32_t)__bfloat16_as_ushort(h1) << 16);
        uint32_t ph1 = (uint32_t)__bfloat16_as_ushort(h2) | ((uint32_t)__bfloat16_as_ushort(h3) << 16);
        uint32_t pl0 = (uint32_t)__bfloat16_as_ushort(l0) | ((uint32_t)__bfloat16_as_ushort(l1) << 16);
        uint32_t pl1 = (uint32_t)__bfloat16_as_ushort(l2) | ((uint32_t)__bfloat16_as_ushort(l3) << 16);
        ((uint2*)g_xh)[i] = make_uint2(ph0, ph1);
        ((uint2*)g_xl)[i] = make_uint2(pl0, pl1);
    }
}

// in: [E][K][N] fp32 -> out: [E][N][K] bf16 hi/lo
__global__ void transpose_cvt(const float* __restrict__ in,
                              __nv_bfloat16* __restrict__ oh,
                              __nv_bfloat16* __restrict__ ol,
                              int K, int N) {
    __shared__ float t[32][33];
    const int e = blockIdx.z;
    const float* src = in + (size_t)e * K * N;
    __nv_bfloat16* dh = oh + (size_t)e * K * N;
    __nv_bfloat16* dl = ol + (size_t)e * K * N;
    const int k0 = blockIdx.x * 32, n0 = blockIdx.y * 32;
    const int tx = threadIdx.x, ty = threadIdx.y;
#pragma unroll
    for (int j = 0; j < 32; j += 8)
        t[ty + j][tx] = src[(size_t)(k0 + ty + j) * N + n0 + tx];
    __syncthreads();
#pragma unroll
    for (int j = 0; j < 32; j += 8) {
        float v = t[tx][ty + j];
        __nv_bfloat16 h = __float2bfloat16(v);
        size_t o = (size_t)(n0 + ty + j) * K + k0 + tx;
        dh[o] = h;
        dl[o] = __float2bfloat16(v - __bfloat162float(h));
    }
}

// ---------------------------------------------------------------------------
// Fused gate+up grouped GEMM: CTA tile M=128 x N=64 (per matrix), BK=32.
// 8 warps (4 along M x 2 along N), each warp 32x32 per matrix.
// smem per buffer: Ah,Al (128x80) + Bgh,Bgl,Buh,Bul (64x80) = 40960 B; x2
// ---------------------------------------------------------------------------
#define GU_BUF 40960
#define GU_SMEM (2 * GU_BUF)

__global__ void __launch_bounds__(256) k_gateup() {
    const int t = blockIdx.y;
    if (t >= g_ntiles) return;
    const int e     = g_tile_expert[t];
    const int row0  = g_tile_row0[t];
    const int nrows = g_tile_nrows[t];
    const int n0    = blockIdx.x * 64;

    extern __shared__ char smem[];
    const uint32_t sb = smem_u32(smem);
    const int tid  = threadIdx.x;
    const int lane = tid & 31;
    const int wid  = tid >> 5;
    const int wm   = wid & 3;   // 0..3 -> rows wm*32
    const int wn   = wid >> 2;  // 0..1 -> cols wn*32

    const __nv_bfloat16* xh = g_xh + (size_t)row0 * HID;
    const __nv_bfloat16* xl = g_xl + (size_t)row0 * HID;
    const size_t wbase = (size_t)e * INTER * HID + (size_t)n0 * HID;
    const __nv_bfloat16* gh = g_wgh + wbase;
    const __nv_bfloat16* gl = g_wgl + wbase;
    const __nv_bfloat16* uh = g_wuh + wbase;
    const __nv_bfloat16* ul = g_wul + wbase;

    float cg[2][4][4], cu[2][4][4];
#pragma unroll
    for (int i = 0; i < 2; i++)
#pragma unroll
        for (int j = 0; j < 4; j++)
#pragma unroll
            for (int k = 0; k < 4; k++) { cg[i][j][k] = 0.f; cu[i][j][k] = 0.f; }

#define GU_LOAD(b, k0)                                              \
    do {                                                            \
        uint32_t o = sb + (b) * GU_BUF;                             \
        load_tile128(o,          xh, HID, (k0), nrows, tid);        \
        load_tile128(o + 10240,  xl, HID, (k0), nrows, tid);        \
        load_tile64(o + 20480,   gh, HID, (k0), tid);               \
        load_tile64(o + 25600,   gl, HID, (k0), tid);               \
        load_tile64(o + 30720,   uh, HID, (k0), tid);               \
        load_tile64(o + 35840,   ul, HID, (k0), tid);               \
        CP_COMMIT();                                                \
    } while (0)

    GU_LOAD(0, 0);
    const int KT = HID / 32;
    for (int kt = 0; kt < KT; kt++) {
        const bool more = (kt + 1 < KT);
        if (more) GU_LOAD((kt + 1) & 1, (kt + 1) * 32);
        if (more) CP_WAIT1(); else CP_WAIT0();
        __syncthreads();
        const char* buf = smem + (kt & 1) * GU_BUF;
#pragma unroll
        for (int ks = 0; ks < 2; ks++) {
            const int k0 = ks * 16;
            uint32_t ah0[4], ah1[4], al0[4], al1[4];
            ldfragA(ah0, buf,          wm * 32,      k0, lane);
            ldfragA(ah1, buf,          wm * 32 + 16, k0, lane);
            ldfragA(al0, buf + 10240,  wm * 32,      k0, lane);
            ldfragA(al1, buf + 10240,  wm * 32 + 16, k0, lane);
#pragma unroll
            for (int nt = 0; nt < 4; nt++) {
                const int nb = wn * 32 + nt * 8;
                uint32_t bgh[2], bgl[2], buh[2], bul[2];
                ldfragB(bgh, buf + 20480, nb, k0, lane);
                ldfragB(bgl, buf + 25600, nb, k0, lane);
                ldfragB(buh, buf + 30720, nb, k0, lane);
                ldfragB(bul, buf + 35840, nb, k0, lane);
                MMA(cg[0][nt], ah0, bgh); MMA(cg[0][nt], ah0, bgl); MMA(cg[0][nt], al0, bgh);
                MMA(cg[1][nt], ah1, bgh); MMA(cg[1][nt], ah1, bgl); MMA(cg[1][nt], al1, bgh);
                MMA(cu[0][nt], ah0, buh); MMA(cu[0][nt], ah0, bul); MMA(cu[0][nt], al0, buh);
                MMA(cu[1][nt], ah1, buh); MMA(cu[1][nt], ah1, bul); MMA(cu[1][nt], al1, buh);
            }
        }
        __syncthreads();
    }

    // epilogue: silu(gate)*up -> h hi/lo
#pragma unroll
    for (int mt = 0; mt < 2; mt++)
#pragma unroll
        for (int half = 0; half < 2; half++) {
            const int r = wm * 32 + mt * 16 + half * 8 + (lane >> 2);
            if (r < nrows) {
                __nv_bfloat16* hhp = g_hh + (size_t)(row0 + r) * INTER + n0 + wn * 32;
                __nv_bfloat16* hlp = g_hl + (size_t)(row0 + r) * INTER + n0 + wn * 32;
#pragma unroll
                for (int nt = 0; nt < 4; nt++) {
                    const float gg0 = cg[mt][nt][half * 2], gg1 = cg[mt][nt][half * 2 + 1];
                    const float uu0 = cu[mt][nt][half * 2], uu1 = cu[mt][nt][half * 2 + 1];
                    const float h0 = uu0 * gg0 / (1.f + __expf(-gg0));
                    const float h1 = uu1 * gg1 / (1.f + __expf(-gg1));
                    const __nv_bfloat16 hh0 = __float2bfloat16(h0);
                    const __nv_bfloat16 hh1 = __float2bfloat16(h1);
                    const __nv_bfloat16 ll0 = __float2bfloat16(h0 - __bfloat162float(hh0));
                    const __nv_bfloat16 ll1 = __float2bfloat16(h1 - __bfloat162float(hh1));
                    const int col = nt * 8 + (lane & 3) * 2;
                    *(uint32_t*)(hhp + col) =
                        (uint32_t)__bfloat16_as_ushort(hh0) | ((uint32_t)__bfloat16_as_ushort(hh1) << 16);
                    *(uint32_t*)(hlp + col) =
                        (uint32_t)__bfloat16_as_ushort(ll0) | ((uint32_t)__bfloat16_as_ushort(ll1) << 16);
                }
            }
        }
}

// ---------------------------------------------------------------------------
// Down grouped GEMM: CTA tile M=128 x N=128, BK=32. out = probs * (h @ WdT)
// 8 warps (4 x 2), each warp 32x64. smem/buffer: Ah,Al,Bh,Bl 128x80 = 40960; x2
// ---------------------------------------------------------------------------
#define DN_BUF 40960
#define DN_SMEM (2 * DN_BUF)

__global__ void __launch_bounds__(256) k_down(const float* __restrict__ probs,
                                              float* __restrict__ out) {
    const int t = blockIdx.y;
    if (t >= g_ntiles) return;
    const int e     = g_tile_expert[t];
    const int row0  = g_tile_row0[t];
    const int nrows = g_tile_nrows[t];
    const int n0    = blockIdx.x * 128;

    extern __shared__ char smem[];
    const uint32_t sb = smem_u32(smem);
    const int tid  = threadIdx.x;
    const int lane = tid & 31;
    const int wid  = tid >> 5;
    const int wm   = wid & 3;
    const int wn   = wid >> 2;  // 0..1 -> cols wn*64

    const __nv_bfloat16* ah = g_hh + (size_t)row0 * INTER;
    const __nv_bfloat16* al = g_hl + (size_t)row0 * INTER;
    const size_t wbase = (size_t)e * HID * INTER + (size_t)n0 * INTER;
    const __nv_bfloat16* bh = g_wdh + wbase;
    const __nv_bfloat16* blo = g_wdl + wbase;

    float cc[2][8][4];
#pragma unroll
    for (int i = 0; i < 2; i++)
#pragma unroll
        for (int j = 0; j < 8; j++)
#pragma unroll
            for (int k = 0; k < 4; k++) cc[i][j][k] = 0.f;

#define DN_LOAD(b, k0)                                               \
    do {                                                             \
        uint32_t o = sb + (b) * DN_BUF;                              \
        load_tile128(o,          ah,  INTER, (k0), nrows, tid);      \
        load_tile128(o + 10240,  al,  INTER, (k0), nrows, tid);      \
        load_tile128(o + 20480,  bh,  INTER, (k0), 128,   tid);      \
        load_tile128(o + 30720,  blo, INTER, (k0), 128,   tid);      \
        CP_COMMIT();                                                 \
    } while (0)

    DN_LOAD(0, 0);
    const int KT = INTER / 32;
    for (int kt = 0; kt < KT; kt++) {
        const bool more = (kt + 1 < KT);
        if (more) DN_LOAD((kt + 1) & 1, (kt + 1) * 32);
        if (more) CP_WAIT1(); else CP_WAIT0();
        __syncthreads();
        const char* buf = smem + (kt & 1) * DN_BUF;
#pragma unroll
        for (int ks = 0; ks < 2; ks++) {
            const int k0 = ks * 16;
            uint32_t ah0[4], ah1[4], al0[4], al1[4];
            ldfragA(ah0, buf,         wm * 32,      k0, lane);
            ldfragA(ah1, buf,         wm * 32 + 16, k0, lane);
            ldfragA(al0, buf + 10240, wm * 32,      k0, lane);
            ldfragA(al1, buf + 10240, wm * 32 + 16, k0, lane);
#pragma unroll
            for (int nt = 0; nt < 8; nt++) {
                const int nb = wn * 64 + nt * 8;
                uint32_t fbh[2], fbl[2];
                ldfragB(fbh, buf + 20480, nb, k0, lane);
                ldfragB(fbl, buf + 30720, nb, k0, lane);
                MMA(cc[0][nt], ah0, fbh); MMA(cc[0][nt], ah0, fbl); MMA(cc[0][nt], al0, fbh);
                MMA(cc[1][nt], ah1, fbh); MMA(cc[1][nt], ah1, fbl); MMA(cc[1][nt], al1, fbh);
            }
        }
        __syncthreads();
    }

    // epilogue: scale by probs, write fp32 out
#pragma unroll
    for (int mt = 0; mt < 2; mt++)
#pragma unroll
        for (int half = 0; half < 2; half++) {
            const int r = wm * 32 + mt * 16 + half * 8 + (lane >> 2);
            if (r < nrows) {
                const float p = probs[row0 + r];
                float* op = out + (size_t)(row0 + r) * HID + n0 + wn * 64;
#pragma unroll
                for (int nt = 0; nt < 8; nt++) {
                    const int col = nt * 8 + (lane & 3) * 2;
                    float2 v;
                    v.x = p * cc[mt][nt][half * 2];
                    v.y = p * cc[mt][nt][half * 2 + 1];
                    *(float2*)(op + col) = v;
                }
            }
        }
}

// ---------------------------------------------------------------------------
// Launch
// ---------------------------------------------------------------------------
extern "C" void kernel_launch(void* const* d_in, const int* in_sizes, int n_in,
                              void* d_out, int out_size) {
    const float* x     = (const float*)d_in[0];
    const float* probs = (const float*)d_in[1];
    const float* wg    = (const float*)d_in[2];
    const float* wu    = (const float*)d_in[3];
    const float* wd    = (const float*)d_in[4];
    const int*   tpe   = (const int*)d_in[5];
    float*       out   = (float*)d_out;

    cudaFuncSetAttribute(k_gateup, cudaFuncAttributeMaxDynamicSharedMemorySize, GU_SMEM);
    cudaFuncSetAttribute(k_down,   cudaFuncAttributeMaxDynamicSharedMemorySize, DN_SMEM);

    setup_tiles<<<1, 1>>>(tpe);
    convert_x<<<2048, 256>>>(x);

    __nv_bfloat16 *wgh, *wgl, *wuh, *wul, *wdh, *wdl;
    cudaGetSymbolAddress((void**)&wgh, g_wgh);
    cudaGetSymbolAddress((void**)&wgl, g_wgl);
    cudaGetSymbolAddress((void**)&wuh, g_wuh);
    cudaGetSymbolAddress((void**)&wul, g_wul);
    cudaGetSymbolAddress((void**)&wdh, g_wdh);
    cudaGetSymbolAddress((void**)&wdl, g_wdl);

    dim3 tb(32, 8);
    transpose_cvt<<<dim3(HID / 32, INTER / 32, NE), tb>>>(wg, wgh, wgl, HID, INTER);
    transpose_cvt<<<dim3(HID / 32, INTER / 32, NE), tb>>>(wu, wuh, wul, HID, INTER);
    transpose_cvt<<<dim3(INTER / 32, HID / 32, NE), tb>>>(wd, wdh, wdl, INTER, HID);

    k_gateup<<<dim3(INTER / 64, MAXGRIDY), 256, GU_SMEM>>>();
    k_down<<<dim3(HID / 128, MAXGRIDY), 256, DN_SMEM>>>(probs, out);
}